// round 1
// baseline (speedup 1.0000x reference)
#include <cuda_runtime.h>
#include <math.h>

#define MAXSEG 100
#define C2MAX 200
#define DDIM 768
#define NMAX 32768

// ---- device scratch (no allocations allowed) ----
__device__ int   g_counts[MAXSEG];
__device__ int   g_offsets[MAXSEG + 1];
__device__ int   g_cursor[MAXSEG];
__device__ int   g_idx[NMAX];
__device__ int   g_valid[C2MAX];
__device__ int   g_nvalid;
__device__ float g_znorm[C2MAX * DDIM];
__device__ float g_logits[C2MAX * C2MAX];

// ---------------------------------------------------------------------------
// 1. zero counters
__global__ void zero_kernel() {
    int t = threadIdx.x;
    if (t < MAXSEG) { g_counts[t] = 0; }
}

// 2. histogram of labels (smem-privatized)
__global__ void hist_kernel(const int* __restrict__ labels, int N) {
    __shared__ int h[MAXSEG];
    for (int i = threadIdx.x; i < MAXSEG; i += blockDim.x) h[i] = 0;
    __syncthreads();
    int i = blockIdx.x * blockDim.x + threadIdx.x;
    if (i < N) atomicAdd(&h[labels[i]], 1);
    __syncthreads();
    for (int i2 = threadIdx.x; i2 < MAXSEG; i2 += blockDim.x)
        if (h[i2]) atomicAdd(&g_counts[i2], h[i2]);
}

// 3. exclusive prefix + valid flags (tiny, 1 thread)
__global__ void prefix_kernel(const int* __restrict__ task) {
    int end_i = (task[0] + 1) * 10;
    if (end_i > MAXSEG) end_i = MAXSEG;
    int run = 0, nv = 0;
    for (int s = 0; s < end_i; s++) {
        g_offsets[s] = run;
        g_cursor[s]  = run;
        int c = g_counts[s];
        run += c;
        int v = (c > 0) ? 1 : 0;
        g_valid[s] = v;
        g_valid[s + end_i] = v;
        nv += 2 * v;
    }
    g_offsets[end_i] = run;
    g_nvalid = nv;
}

// 4. scatter row indices into per-segment buckets
__global__ void scatter_kernel(const int* __restrict__ labels, int N) {
    int i = blockIdx.x * blockDim.x + threadIdx.x;
    if (i < N) {
        int l = labels[i];
        int p = atomicAdd(&g_cursor[l], 1);
        g_idx[p] = i;
    }
}

// 5. segment sums -> prototypes (THE hot kernel: 192 MB streaming read)
//    grid (100 segs, 4 col-chunks of 192), block 192 threads.
//    Each z element is read exactly once; writes go straight to d_out.
__global__ void segsum_kernel(const float* __restrict__ z1,
                              const float* __restrict__ z2,
                              const int* __restrict__ task,
                              float* __restrict__ out) {
    __shared__ int sidx[1024];
    int seg = blockIdx.x;
    int end_i = (task[0] + 1) * 10;
    if (end_i > MAXSEG) end_i = MAXSEG;
    if (seg >= end_i) return;
    int col = blockIdx.y * 192 + threadIdx.x;
    int beg = g_offsets[seg], end = g_offsets[seg + 1];

    float a0 = 0.f, a1 = 0.f, a2 = 0.f, a3 = 0.f;
    float b0 = 0.f, b1 = 0.f, b2 = 0.f, b3 = 0.f;

    for (int cb = beg; cb < end; cb += 1024) {
        int cn = end - cb; if (cn > 1024) cn = 1024;
        __syncthreads();
        for (int t = threadIdx.x; t < cn; t += 192) sidx[t] = g_idx[cb + t];
        __syncthreads();
        int k = 0;
        for (; k + 4 <= cn; k += 4) {
            int r0 = sidx[k] * DDIM + col;
            int r1 = sidx[k + 1] * DDIM + col;
            int r2 = sidx[k + 2] * DDIM + col;
            int r3 = sidx[k + 3] * DDIM + col;
            a0 += z1[r0]; a1 += z1[r1]; a2 += z1[r2]; a3 += z1[r3];
            b0 += z2[r0]; b1 += z2[r1]; b2 += z2[r2]; b3 += z2[r3];
        }
        for (; k < cn; k++) {
            int r = sidx[k] * DDIM + col;
            a0 += z1[r]; b0 += z2[r];
        }
    }
    float cnt   = (float)(end - beg);
    float denom = fmaxf(cnt, 1.0f);
    float p1 = ((a0 + a1) + (a2 + a3)) / denom;
    float p2 = ((b0 + b1) + (b2 + b3)) / denom;
    out[1 + seg * DDIM + col] = p1;
    out[1 + (end_i + seg) * DDIM + col] = p2;
}

// 6. l2-normalize prototypes, fold sqrt(2) temperature factor, write znorm
__global__ void norm_kernel(const float* __restrict__ out,
                            const int* __restrict__ task) {
    int end_i = (task[0] + 1) * 10;
    if (end_i > MAXSEG) end_i = MAXSEG;
    int C2 = 2 * end_i;
    int r = blockIdx.x;
    if (r >= C2) return;
    const float* p = out + 1 + r * DDIM;
    float ss = 0.f;
    for (int c = threadIdx.x; c < DDIM; c += 256) { float v = p[c]; ss += v * v; }
    __shared__ float red[8];
    for (int o = 16; o; o >>= 1) ss += __shfl_xor_sync(0xFFFFFFFFu, ss, o);
    if ((threadIdx.x & 31) == 0) red[threadIdx.x >> 5] = ss;
    __syncthreads();
    __shared__ float s_scale;
    if (threadIdx.x == 0) {
        float t = 0.f;
        #pragma unroll
        for (int k = 0; k < 8; k++) t += red[k];
        s_scale = 1.41421356237309515f / fmaxf(sqrtf(t), 1e-12f);
    }
    __syncthreads();
    float sc = s_scale;
    for (int c = threadIdx.x; c < DDIM; c += 256)
        g_znorm[r * DDIM + c] = p[c] * sc;
}

// 7. logits = znorm @ znorm^T  (200x200x768, tiled 16x16, K-chunks of 192)
#define GT 16
#define GKC 192
__global__ void gemm_kernel(const int* __restrict__ task) {
    int end_i = (task[0] + 1) * 10;
    if (end_i > MAXSEG) end_i = MAXSEG;
    int C2 = 2 * end_i;
    __shared__ float As[GT][GKC + 1];
    __shared__ float Bs[GT][GKC + 1];
    int tx = threadIdx.x & 15;
    int ty = threadIdx.x >> 4;
    int row0 = blockIdx.y * GT, col0 = blockIdx.x * GT;
    float acc0 = 0.f, acc1 = 0.f, acc2 = 0.f, acc3 = 0.f;
    for (int kb = 0; kb < DDIM; kb += GKC) {
        for (int l = threadIdx.x; l < GT * GKC; l += 256) {
            int rr = l / GKC, kk = l - rr * GKC;
            As[rr][kk] = (row0 + rr < C2) ? g_znorm[(row0 + rr) * DDIM + kb + kk] : 0.f;
            Bs[rr][kk] = (col0 + rr < C2) ? g_znorm[(col0 + rr) * DDIM + kb + kk] : 0.f;
        }
        __syncthreads();
        #pragma unroll 12
        for (int k = 0; k < GKC; k += 4) {
            acc0 += As[ty][k]     * Bs[tx][k];
            acc1 += As[ty][k + 1] * Bs[tx][k + 1];
            acc2 += As[ty][k + 2] * Bs[tx][k + 2];
            acc3 += As[ty][k + 3] * Bs[tx][k + 3];
        }
        __syncthreads();
    }
    int r = row0 + ty, c = col0 + tx;
    if (r < C2 && c < C2)
        g_logits[r * C2MAX + c] = (acc0 + acc1) + (acc2 + acc3);
}

// 8. loss: per-row masked max / logsumexp / positive-pair pick, reduce
__global__ void loss_kernel(const int* __restrict__ task, float* __restrict__ out) {
    int end_i = (task[0] + 1) * 10;
    if (end_i > MAXSEG) end_i = MAXSEG;
    int C2 = 2 * end_i;
    int lane = threadIdx.x & 31;
    int w = threadIdx.x >> 5;                 // 8 warps
    __shared__ float wloss[8];
    float acc = 0.f;
    for (int i = w; i < C2; i += 8) {
        if (!g_valid[i]) continue;            // uniform per warp
        const float* Li = &g_logits[i * C2MAX];
        float m = -INFINITY;
        for (int j = lane; j < C2; j += 32)
            if (g_valid[j]) m = fmaxf(m, Li[j]);
        for (int o = 16; o; o >>= 1) m = fmaxf(m, __shfl_xor_sync(0xFFFFFFFFu, m, o));
        float s = 0.f;
        for (int j = lane; j < C2; j += 32)
            if (g_valid[j] && j != i) s += expf(Li[j] - m);
        for (int o = 16; o; o >>= 1) s += __shfl_xor_sync(0xFFFFFFFFu, s, o);
        if (lane == 0) {
            int p = i + end_i; if (p >= C2) p -= C2;
            acc += (Li[p] - m) - logf(s);
        }
    }
    if (lane == 0) wloss[w] = acc;
    __syncthreads();
    if (threadIdx.x == 0) {
        float t = 0.f;
        #pragma unroll
        for (int k = 0; k < 8; k++) t += wloss[k];
        float nv = (float)g_nvalid;
        out[0] = -t / fmaxf(nv, 1.0f);
    }
}

// ---------------------------------------------------------------------------
extern "C" void kernel_launch(void* const* d_in, const int* in_sizes, int n_in,
                              void* d_out, int out_size) {
    const float* z1     = (const float*)d_in[0];
    const float* z2     = (const float*)d_in[1];
    const int*   labels = (const int*)d_in[2];
    const int*   task   = (const int*)d_in[3];
    float* out = (float*)d_out;
    int N = in_sizes[2];

    zero_kernel<<<1, 128>>>();
    hist_kernel<<<(N + 255) / 256, 256>>>(labels, N);
    prefix_kernel<<<1, 1>>>(task);
    scatter_kernel<<<(N + 255) / 256, 256>>>(labels, N);

    dim3 sgrid(MAXSEG, DDIM / 192);          // (100, 4)
    segsum_kernel<<<sgrid, 192>>>(z1, z2, task, out);

    norm_kernel<<<C2MAX, 256>>>(out, task);

    dim3 ggrid((C2MAX + GT - 1) / GT, (C2MAX + GT - 1) / GT);  // 13x13
    gemm_kernel<<<ggrid, 256>>>(task);

    loss_kernel<<<1, 256>>>(task, out);
}

// round 5
// speedup vs baseline: 1.3859x; 1.3859x over previous
#include <cuda_runtime.h>
#include <math.h>

#define MAXSEG 100
#define C2MAX 200
#define DDIM 768
#define D4 192          // DDIM / 4
#define NMAX 32768
#define RC 8            // row-chunks per segment in segsum
#define PB 128          // prep blocks
#define PT 256          // prep threads

// ---- device scratch (no allocations allowed) ----
__device__ int   g_hist[PB * MAXSEG];
__device__ int   g_offsets[MAXSEG + 1];
__device__ int   g_idx[NMAX];
__device__ int   g_valid[C2MAX];
__device__ int   g_nvalid;
__device__ float g_part1[RC * MAXSEG * DDIM];
__device__ float g_part2[RC * MAXSEG * DDIM];
__device__ float g_znorm[C2MAX * DDIM];
__device__ float g_logits[C2MAX * C2MAX];

// ---------------------------------------------------------------------------
// 1a. per-block label histograms (no inter-block sync)
__global__ void __launch_bounds__(PT) prep_hist_kernel(const int* __restrict__ labels,
                                                       const int* __restrict__ task,
                                                       int N) {
    __shared__ int h[MAXSEG];
    int b = blockIdx.x, t = threadIdx.x;
    int end_i = (task[0] + 1) * 10;
    if (end_i > MAXSEG) end_i = MAXSEG;

    for (int i = t; i < MAXSEG; i += PT) h[i] = 0;
    __syncthreads();

    int per = (N + PB * PT - 1) / (PB * PT);
    int lo = b * PT * per;
    int hi = lo + PT * per; if (hi > N) hi = N;
    for (int i = lo + t; i < hi; i += PT) {
        int l = labels[i];
        if (l < end_i) atomicAdd(&h[l], 1);
    }
    __syncthreads();
    for (int i = t; i < MAXSEG; i += PT) g_hist[b * MAXSEG + i] = h[i];
}

// 1b. each block recomputes global prefix from g_hist, scatters its own range
__global__ void __launch_bounds__(PT) prep_scatter_kernel(const int* __restrict__ labels,
                                                          const int* __restrict__ task,
                                                          int N) {
    __shared__ int tot[MAXSEG];    // per-label total counts
    __shared__ int pre[MAXSEG];    // counts in blocks before this one
    __shared__ int off[MAXSEG];    // global exclusive prefix
    __shared__ int cur[MAXSEG];    // scatter cursor for this block
    int b = blockIdx.x, t = threadIdx.x;
    int end_i = (task[0] + 1) * 10;
    if (end_i > MAXSEG) end_i = MAXSEG;

    for (int l = t; l < end_i; l += PT) {
        int p = 0, s = 0;
        #pragma unroll 1
        for (int bb = 0; bb < PB; bb++) {
            int v = g_hist[bb * MAXSEG + l];
            if (bb < b) p += v;
            s += v;
        }
        pre[l] = p;
        tot[l] = s;
    }
    __syncthreads();
    if (t == 0) {
        int run = 0;
        #pragma unroll 1
        for (int l = 0; l < end_i; l++) { off[l] = run; run += tot[l]; }
        if (b == 0) {
            int nv = 0;
            #pragma unroll 1
            for (int l = 0; l < end_i; l++) {
                g_offsets[l] = off[l];
                int v = (tot[l] > 0) ? 1 : 0;
                g_valid[l] = v;
                g_valid[l + end_i] = v;
                nv += 2 * v;
            }
            g_offsets[end_i] = run;
            g_nvalid = nv;
        }
    }
    __syncthreads();
    for (int l = t; l < end_i; l += PT) cur[l] = off[l] + pre[l];
    __syncthreads();

    int per = (N + PB * PT - 1) / (PB * PT);
    int lo = b * PT * per;
    int hi = lo + PT * per; if (hi > N) hi = N;
    for (int i = lo + t; i < hi; i += PT) {
        int l = labels[i];
        if (l < end_i) {
            int p = atomicAdd(&cur[l], 1);
            g_idx[p] = i;
        }
    }
}

// ---------------------------------------------------------------------------
// 2. segsum: 192 MB streaming gather, float4, 8 row-chunks/segment, no atomics
__global__ void __launch_bounds__(D4, 1) segsum_kernel(const float4* __restrict__ z1,
                                                       const float4* __restrict__ z2,
                                                       const int* __restrict__ task) {
    __shared__ int sidx[4096];
    __shared__ int s_range[2];
    int seg = blockIdx.x, rc = blockIdx.y;
    int end_i = (task[0] + 1) * 10;
    if (end_i > MAXSEG) end_i = MAXSEG;
    if (seg >= end_i) return;

    if (threadIdx.x == 0) {
        s_range[0] = g_offsets[seg];
        s_range[1] = g_offsets[seg + 1];
    }
    __syncthreads();
    int beg = s_range[0], end = s_range[1];
    int total = end - beg;
    int per = (total + RC - 1) / RC;
    int s0 = beg + rc * per;
    int n = end - s0; if (n > per) n = per; if (n < 0) n = 0;

    for (int t = threadIdx.x; t < n; t += D4) sidx[t] = g_idx[s0 + t];
    __syncthreads();

    int tx = threadIdx.x;
    float4 a0 = {0,0,0,0}, a1 = {0,0,0,0};
    float4 b0 = {0,0,0,0}, b1 = {0,0,0,0};

    int k = 0;
    for (; k + 4 <= n; k += 4) {
        int r0 = sidx[k]     * D4 + tx;
        int r1 = sidx[k + 1] * D4 + tx;
        int r2 = sidx[k + 2] * D4 + tx;
        int r3 = sidx[k + 3] * D4 + tx;
        float4 x0 = z1[r0], x1 = z1[r1], x2 = z1[r2], x3 = z1[r3];
        float4 y0 = z2[r0], y1 = z2[r1], y2 = z2[r2], y3 = z2[r3];
        a0.x += x0.x + x1.x; a0.y += x0.y + x1.y; a0.z += x0.z + x1.z; a0.w += x0.w + x1.w;
        a1.x += x2.x + x3.x; a1.y += x2.y + x3.y; a1.z += x2.z + x3.z; a1.w += x2.w + x3.w;
        b0.x += y0.x + y1.x; b0.y += y0.y + y1.y; b0.z += y0.z + y1.z; b0.w += y0.w + y1.w;
        b1.x += y2.x + y3.x; b1.y += y2.y + y3.y; b1.z += y2.z + y3.z; b1.w += y2.w + y3.w;
    }
    for (; k < n; k++) {
        int r = sidx[k] * D4 + tx;
        float4 x = z1[r], y = z2[r];
        a0.x += x.x; a0.y += x.y; a0.z += x.z; a0.w += x.w;
        b0.x += y.x; b0.y += y.y; b0.z += y.z; b0.w += y.w;
    }
    float4 A = {a0.x + a1.x, a0.y + a1.y, a0.z + a1.z, a0.w + a1.w};
    float4 B = {b0.x + b1.x, b0.y + b1.y, b0.z + b1.z, b0.w + b1.w};
    ((float4*)g_part1)[(rc * MAXSEG + seg) * D4 + tx] = A;
    ((float4*)g_part2)[(rc * MAXSEG + seg) * D4 + tx] = B;
}

// ---------------------------------------------------------------------------
// 3. finalize + l2-normalize (folds sqrt(2) temperature factor into znorm)
//    NOTE: stores to `out` are SCALAR — out+1 is only 4-byte aligned.
__global__ void __launch_bounds__(D4) finalize_norm_kernel(const int* __restrict__ task,
                                                           float* __restrict__ out) {
    int end_i = (task[0] + 1) * 10;
    if (end_i > MAXSEG) end_i = MAXSEG;
    int C2 = 2 * end_i;
    int r = blockIdx.x;
    if (r >= C2) return;
    int seg = (r < end_i) ? r : r - end_i;
    const float4* P = (const float4*)((r < end_i) ? g_part1 : g_part2);

    int cnt = g_offsets[seg + 1] - g_offsets[seg];
    float inv = 1.0f / fmaxf((float)cnt, 1.0f);

    int tx = threadIdx.x;
    float4 s = {0,0,0,0};
    #pragma unroll
    for (int rc = 0; rc < RC; rc++) {
        float4 v = P[(rc * MAXSEG + seg) * D4 + tx];
        s.x += v.x; s.y += v.y; s.z += v.z; s.w += v.w;
    }
    s.x *= inv; s.y *= inv; s.z *= inv; s.w *= inv;
    // scalar stores (out+1 is 4B-aligned only)
    float* op = out + 1 + r * DDIM + tx * 4;
    op[0] = s.x; op[1] = s.y; op[2] = s.z; op[3] = s.w;

    float ss = s.x*s.x + s.y*s.y + s.z*s.z + s.w*s.w;
    for (int o = 16; o; o >>= 1) ss += __shfl_xor_sync(0xFFFFFFFFu, ss, o);
    __shared__ float red[6];
    if ((tx & 31) == 0) red[tx >> 5] = ss;
    __syncthreads();
    __shared__ float s_scale;
    if (tx == 0) {
        float t = 0.f;
        #pragma unroll
        for (int k = 0; k < 6; k++) t += red[k];
        s_scale = 1.41421356237309515f / fmaxf(sqrtf(t), 1e-12f);
    }
    __syncthreads();
    float sc = s_scale;
    float4 zn = {s.x * sc, s.y * sc, s.z * sc, s.w * sc};
    ((float4*)g_znorm)[r * D4 + tx] = zn;
}

// ---------------------------------------------------------------------------
// 4. logits = znorm @ znorm^T  (200x200x768, tiled 16x16)
#define GT 16
#define GKC 192
__global__ void gemm_kernel(const int* __restrict__ task) {
    int end_i = (task[0] + 1) * 10;
    if (end_i > MAXSEG) end_i = MAXSEG;
    int C2 = 2 * end_i;
    __shared__ float As[GT][GKC + 1];
    __shared__ float Bs[GT][GKC + 1];
    int tx = threadIdx.x & 15;
    int ty = threadIdx.x >> 4;
    int row0 = blockIdx.y * GT, col0 = blockIdx.x * GT;
    float acc0 = 0.f, acc1 = 0.f, acc2 = 0.f, acc3 = 0.f;
    for (int kb = 0; kb < DDIM; kb += GKC) {
        for (int l = threadIdx.x; l < GT * GKC; l += 256) {
            int rr = l / GKC, kk = l - rr * GKC;
            As[rr][kk] = (row0 + rr < C2) ? g_znorm[(row0 + rr) * DDIM + kb + kk] : 0.f;
            Bs[rr][kk] = (col0 + rr < C2) ? g_znorm[(col0 + rr) * DDIM + kb + kk] : 0.f;
        }
        __syncthreads();
        #pragma unroll 12
        for (int k = 0; k < GKC; k += 4) {
            acc0 += As[ty][k]     * Bs[tx][k];
            acc1 += As[ty][k + 1] * Bs[tx][k + 1];
            acc2 += As[ty][k + 2] * Bs[tx][k + 2];
            acc3 += As[ty][k + 3] * Bs[tx][k + 3];
        }
        __syncthreads();
    }
    int r = row0 + ty, c = col0 + tx;
    if (r < C2 && c < C2)
        g_logits[r * C2MAX + c] = (acc0 + acc1) + (acc2 + acc3);
}

// ---------------------------------------------------------------------------
// 5. loss: per-row masked max / logsumexp / positive pair, single block
__global__ void loss_kernel(const int* __restrict__ task, float* __restrict__ out) {
    int end_i = (task[0] + 1) * 10;
    if (end_i > MAXSEG) end_i = MAXSEG;
    int C2 = 2 * end_i;
    int lane = threadIdx.x & 31;
    int w = threadIdx.x >> 5;                 // 8 warps
    __shared__ float wloss[8];
    float acc = 0.f;
    for (int i = w; i < C2; i += 8) {
        if (!g_valid[i]) continue;            // uniform per warp
        const float* Li = &g_logits[i * C2MAX];
        float m = -INFINITY;
        for (int j = lane; j < C2; j += 32)
            if (g_valid[j]) m = fmaxf(m, Li[j]);
        for (int o = 16; o; o >>= 1) m = fmaxf(m, __shfl_xor_sync(0xFFFFFFFFu, m, o));
        float s = 0.f;
        for (int j = lane; j < C2; j += 32)
            if (g_valid[j] && j != i) s += expf(Li[j] - m);
        for (int o = 16; o; o >>= 1) s += __shfl_xor_sync(0xFFFFFFFFu, s, o);
        if (lane == 0) {
            int p = i + end_i; if (p >= C2) p -= C2;
            acc += (Li[p] - m) - logf(s);
        }
    }
    if (lane == 0) wloss[w] = acc;
    __syncthreads();
    if (threadIdx.x == 0) {
        float t = 0.f;
        #pragma unroll
        for (int k = 0; k < 8; k++) t += wloss[k];
        float nv = (float)g_nvalid;
        out[0] = -t / fmaxf(nv, 1.0f);
    }
}

// ---------------------------------------------------------------------------
extern "C" void kernel_launch(void* const* d_in, const int* in_sizes, int n_in,
                              void* d_out, int out_size) {
    const float* z1     = (const float*)d_in[0];
    const float* z2     = (const float*)d_in[1];
    const int*   labels = (const int*)d_in[2];
    const int*   task   = (const int*)d_in[3];
    float* out = (float*)d_out;
    int N = in_sizes[2];

    prep_hist_kernel<<<PB, PT>>>(labels, task, N);
    prep_scatter_kernel<<<PB, PT>>>(labels, task, N);

    dim3 sgrid(MAXSEG, RC);                        // (100, 8)
    segsum_kernel<<<sgrid, D4>>>((const float4*)z1, (const float4*)z2, task);

    finalize_norm_kernel<<<C2MAX, D4>>>(task, out);

    dim3 ggrid((C2MAX + GT - 1) / GT, (C2MAX + GT - 1) / GT);  // 13x13
    gemm_kernel<<<ggrid, 256>>>(task);

    loss_kernel<<<1, 256>>>(task, out);
}

// round 6
// speedup vs baseline: 2.0357x; 1.4689x over previous
#include <cuda_runtime.h>
#include <math.h>

#define MAXSEG 100
#define C2MAX 200
#define DDIM 768
#define D4 192          // DDIM / 4
#define NMAX 32768
#define RC 8            // row-chunks per segment in segsum
#define PB 128          // prep blocks
#define PT 256          // prep threads
#define GLB 50          // gemm_loss blocks
#define GLR 4           // rows per gemm_loss block

// ---- device scratch (no allocations allowed) ----
__device__ int   g_hist[PB * MAXSEG];
__device__ int   g_offsets[MAXSEG + 1];
__device__ int   g_idx[NMAX];
__device__ int   g_valid[C2MAX];
__device__ int   g_nvalid;
__device__ int   g_segdone[MAXSEG];
__device__ int   g_gldone;
__device__ float g_blockloss[GLB];
__device__ float g_part1[RC * MAXSEG * DDIM];
__device__ float g_part2[RC * MAXSEG * DDIM];
__device__ float g_znorm[C2MAX * DDIM];

// ---------------------------------------------------------------------------
// 1a. per-block label histograms; block 0 also resets the replay counters
__global__ void __launch_bounds__(PT) prep_hist_kernel(const int* __restrict__ labels,
                                                       const int* __restrict__ task,
                                                       int N) {
    __shared__ int h[MAXSEG];
    int b = blockIdx.x, t = threadIdx.x;
    int end_i = (task[0] + 1) * 10;
    if (end_i > MAXSEG) end_i = MAXSEG;

    if (b == 0) {
        for (int i = t; i < MAXSEG; i += PT) g_segdone[i] = 0;
        if (t == 0) g_gldone = 0;
    }

    for (int i = t; i < MAXSEG; i += PT) h[i] = 0;
    __syncthreads();

    int per = (N + PB * PT - 1) / (PB * PT);
    int lo = b * PT * per;
    int hi = lo + PT * per; if (hi > N) hi = N;
    for (int i = lo + t; i < hi; i += PT) {
        int l = labels[i];
        if (l < end_i) atomicAdd(&h[l], 1);
    }
    __syncthreads();
    for (int i = t; i < MAXSEG; i += PT) g_hist[b * MAXSEG + i] = h[i];
}

// 1b. each block recomputes global prefix from g_hist, scatters its own range
__global__ void __launch_bounds__(PT) prep_scatter_kernel(const int* __restrict__ labels,
                                                          const int* __restrict__ task,
                                                          int N) {
    __shared__ int tot[MAXSEG];
    __shared__ int pre[MAXSEG];
    __shared__ int off[MAXSEG];
    __shared__ int cur[MAXSEG];
    int b = blockIdx.x, t = threadIdx.x;
    int end_i = (task[0] + 1) * 10;
    if (end_i > MAXSEG) end_i = MAXSEG;

    for (int l = t; l < end_i; l += PT) {
        int p = 0, s = 0;
        #pragma unroll 1
        for (int bb = 0; bb < PB; bb++) {
            int v = g_hist[bb * MAXSEG + l];
            if (bb < b) p += v;
            s += v;
        }
        pre[l] = p;
        tot[l] = s;
    }
    __syncthreads();
    if (t == 0) {
        int run = 0;
        #pragma unroll 1
        for (int l = 0; l < end_i; l++) { off[l] = run; run += tot[l]; }
        if (b == 0) {
            int nv = 0;
            #pragma unroll 1
            for (int l = 0; l < end_i; l++) {
                g_offsets[l] = off[l];
                int v = (tot[l] > 0) ? 1 : 0;
                g_valid[l] = v;
                g_valid[l + end_i] = v;
                nv += 2 * v;
            }
            g_offsets[end_i] = run;
            g_nvalid = nv;
        }
    }
    __syncthreads();
    for (int l = t; l < end_i; l += PT) cur[l] = off[l] + pre[l];
    __syncthreads();

    int per = (N + PB * PT - 1) / (PB * PT);
    int lo = b * PT * per;
    int hi = lo + PT * per; if (hi > N) hi = N;
    for (int i = lo + t; i < hi; i += PT) {
        int l = labels[i];
        if (l < end_i) {
            int p = atomicAdd(&cur[l], 1);
            g_idx[p] = i;
        }
    }
}

// ---------------------------------------------------------------------------
// 2. segsum + in-kernel finalize/normalize by the last block of each segment.
//    192 MB streaming gather (__ldcs), float4, RC row-chunks/segment, no data
//    atomics. Last finishing block per segment reduces the RC partials,
//    writes prototypes into d_out and normalized rows (x sqrt2/temp fold)
//    into g_znorm.
__global__ void __launch_bounds__(D4, 1) segsum_kernel(const float4* __restrict__ z1,
                                                       const float4* __restrict__ z2,
                                                       const int* __restrict__ task,
                                                       float* __restrict__ out) {
    __shared__ int sidx[4096];
    __shared__ int s_range[2];
    __shared__ int s_last;
    __shared__ float red[6];
    __shared__ float s_scale;
    int seg = blockIdx.x, rc = blockIdx.y;
    int end_i = (task[0] + 1) * 10;
    if (end_i > MAXSEG) end_i = MAXSEG;
    if (seg >= end_i) return;

    int tx = threadIdx.x;
    if (tx == 0) {
        s_range[0] = g_offsets[seg];
        s_range[1] = g_offsets[seg + 1];
    }
    __syncthreads();
    int beg = s_range[0], end = s_range[1];
    int total = end - beg;
    int per = (total + RC - 1) / RC;
    int s0 = beg + rc * per;
    int n = end - s0; if (n > per) n = per; if (n < 0) n = 0;

    for (int t = tx; t < n; t += D4) sidx[t] = g_idx[s0 + t];
    __syncthreads();

    float4 a0 = {0,0,0,0}, a1 = {0,0,0,0};
    float4 b0 = {0,0,0,0}, b1 = {0,0,0,0};

    int k = 0;
    for (; k + 4 <= n; k += 4) {
        int r0 = sidx[k]     * D4 + tx;
        int r1 = sidx[k + 1] * D4 + tx;
        int r2 = sidx[k + 2] * D4 + tx;
        int r3 = sidx[k + 3] * D4 + tx;
        float4 x0 = __ldcs(z1 + r0), x1 = __ldcs(z1 + r1);
        float4 x2 = __ldcs(z1 + r2), x3 = __ldcs(z1 + r3);
        float4 y0 = __ldcs(z2 + r0), y1 = __ldcs(z2 + r1);
        float4 y2 = __ldcs(z2 + r2), y3 = __ldcs(z2 + r3);
        a0.x += x0.x + x1.x; a0.y += x0.y + x1.y; a0.z += x0.z + x1.z; a0.w += x0.w + x1.w;
        a1.x += x2.x + x3.x; a1.y += x2.y + x3.y; a1.z += x2.z + x3.z; a1.w += x2.w + x3.w;
        b0.x += y0.x + y1.x; b0.y += y0.y + y1.y; b0.z += y0.z + y1.z; b0.w += y0.w + y1.w;
        b1.x += y2.x + y3.x; b1.y += y2.y + y3.y; b1.z += y2.z + y3.z; b1.w += y2.w + y3.w;
    }
    for (; k < n; k++) {
        int r = sidx[k] * D4 + tx;
        float4 x = __ldcs(z1 + r), y = __ldcs(z2 + r);
        a0.x += x.x; a0.y += x.y; a0.z += x.z; a0.w += x.w;
        b0.x += y.x; b0.y += y.y; b0.z += y.z; b0.w += y.w;
    }
    float4 A = {a0.x + a1.x, a0.y + a1.y, a0.z + a1.z, a0.w + a1.w};
    float4 B = {b0.x + b1.x, b0.y + b1.y, b0.z + b1.z, b0.w + b1.w};
    ((float4*)g_part1)[(rc * MAXSEG + seg) * D4 + tx] = A;
    ((float4*)g_part2)[(rc * MAXSEG + seg) * D4 + tx] = B;

    // --- last block of this segment finalizes both prototype rows ---
    __threadfence();
    __syncthreads();
    if (tx == 0) s_last = (atomicAdd(&g_segdone[seg], 1) == RC - 1);
    __syncthreads();
    if (!s_last) return;

    float inv = 1.0f / fmaxf((float)total, 1.0f);
    #pragma unroll
    for (int tensor = 0; tensor < 2; tensor++) {
        const float4* P = tensor ? (const float4*)g_part2 : (const float4*)g_part1;
        float4 s = {0,0,0,0};
        #pragma unroll
        for (int c = 0; c < RC; c++) {
            float4 v = P[(c * MAXSEG + seg) * D4 + tx];
            s.x += v.x; s.y += v.y; s.z += v.z; s.w += v.w;
        }
        s.x *= inv; s.y *= inv; s.z *= inv; s.w *= inv;
        int r = seg + tensor * end_i;
        // scalar stores: out+1 is only 4B-aligned
        float* op = out + 1 + r * DDIM + tx * 4;
        op[0] = s.x; op[1] = s.y; op[2] = s.z; op[3] = s.w;

        float ss = s.x*s.x + s.y*s.y + s.z*s.z + s.w*s.w;
        for (int o = 16; o; o >>= 1) ss += __shfl_xor_sync(0xFFFFFFFFu, ss, o);
        if ((tx & 31) == 0) red[tx >> 5] = ss;
        __syncthreads();
        if (tx == 0) {
            float t = 0.f;
            #pragma unroll
            for (int q = 0; q < 6; q++) t += red[q];
            s_scale = 1.41421356237309515f / fmaxf(sqrtf(t), 1e-12f);
        }
        __syncthreads();
        float sc = s_scale;
        float4 zn = {s.x * sc, s.y * sc, s.z * sc, s.w * sc};
        ((float4*)g_znorm)[r * D4 + tx] = zn;
        __syncthreads();
    }
}

// ---------------------------------------------------------------------------
// 3. fused gemm + loss: 50 blocks x 4 rows. Logits stay in smem; per-block
//    loss contribution; last block reduces in fixed order -> out[0].
__global__ void __launch_bounds__(256) gemm_loss_kernel(const int* __restrict__ task,
                                                        float* __restrict__ out) {
    __shared__ float4 A4[GLR][D4];         // 12 KB
    __shared__ float  lg[GLR][C2MAX];      // 3.2 KB
    __shared__ float  rloss[GLR];
    __shared__ int    s_last;
    int end_i = (task[0] + 1) * 10;
    if (end_i > MAXSEG) end_i = MAXSEG;
    int C2 = 2 * end_i;
    int t = threadIdx.x;
    int lane = t & 31, w = t >> 5;          // 8 warps
    int r0 = blockIdx.x * GLR;

    // load up to GLR znorm rows into smem (zeros past C2)
    for (int i = t; i < GLR * D4; i += 256) {
        int rr = i / D4, cc = i - rr * D4;
        float4 v = {0,0,0,0};
        if (r0 + rr < C2) v = ((const float4*)g_znorm)[(r0 + rr) * D4 + cc];
        A4[rr][cc] = v;
    }
    __syncthreads();

    // dot products: warp w handles columns j = w, w+8, ...
    for (int j = w; j < C2; j += 8) {
        float d0 = 0.f, d1 = 0.f, d2 = 0.f, d3 = 0.f;
        #pragma unroll
        for (int q = 0; q < 6; q++) {
            float4 b = ((const float4*)g_znorm)[j * D4 + lane + 32 * q];
            float4 c0 = A4[0][lane + 32 * q];
            float4 c1 = A4[1][lane + 32 * q];
            float4 c2 = A4[2][lane + 32 * q];
            float4 c3 = A4[3][lane + 32 * q];
            d0 += c0.x*b.x + c0.y*b.y + c0.z*b.z + c0.w*b.w;
            d1 += c1.x*b.x + c1.y*b.y + c1.z*b.z + c1.w*b.w;
            d2 += c2.x*b.x + c2.y*b.y + c2.z*b.z + c2.w*b.w;
            d3 += c3.x*b.x + c3.y*b.y + c3.z*b.z + c3.w*b.w;
        }
        for (int o = 16; o; o >>= 1) {
            d0 += __shfl_xor_sync(0xFFFFFFFFu, d0, o);
            d1 += __shfl_xor_sync(0xFFFFFFFFu, d1, o);
            d2 += __shfl_xor_sync(0xFFFFFFFFu, d2, o);
            d3 += __shfl_xor_sync(0xFFFFFFFFu, d3, o);
        }
        if (lane == 0) {
            lg[0][j] = d0; lg[1][j] = d1; lg[2][j] = d2; lg[3][j] = d3;
        }
    }
    __syncthreads();

    // per-row loss: warp w (w < GLR) handles row r0 + w
    if (w < GLR) {
        int i = r0 + w;
        float rl = 0.f;
        if (i < C2 && g_valid[i]) {
            float m = -INFINITY;
            for (int j = lane; j < C2; j += 32)
                if (g_valid[j]) m = fmaxf(m, lg[w][j]);
            for (int o = 16; o; o >>= 1) m = fmaxf(m, __shfl_xor_sync(0xFFFFFFFFu, m, o));
            float s = 0.f;
            for (int j = lane; j < C2; j += 32)
                if (g_valid[j] && j != i) s += expf(lg[w][j] - m);
            for (int o = 16; o; o >>= 1) s += __shfl_xor_sync(0xFFFFFFFFu, s, o);
            if (lane == 0) {
                int p = i + end_i; if (p >= C2) p -= C2;
                rl = (lg[w][p] - m) - logf(s);
            }
        }
        if (lane == 0) rloss[w] = rl;
    }
    __syncthreads();
    if (t == 0) {
        g_blockloss[blockIdx.x] = (rloss[0] + rloss[1]) + (rloss[2] + rloss[3]);
        __threadfence();
        s_last = (atomicAdd(&g_gldone, 1) == GLB - 1);
    }
    __syncthreads();
    if (t == 0 && s_last) {
        float tot = 0.f;
        #pragma unroll 1
        for (int b = 0; b < GLB; b++) tot += g_blockloss[b];
        out[0] = -tot / fmaxf((float)g_nvalid, 1.0f);
    }
}

// ---------------------------------------------------------------------------
extern "C" void kernel_launch(void* const* d_in, const int* in_sizes, int n_in,
                              void* d_out, int out_size) {
    const float* z1     = (const float*)d_in[0];
    const float* z2     = (const float*)d_in[1];
    const int*   labels = (const int*)d_in[2];
    const int*   task   = (const int*)d_in[3];
    float* out = (float*)d_out;
    int N = in_sizes[2];

    prep_hist_kernel<<<PB, PT>>>(labels, task, N);
    prep_scatter_kernel<<<PB, PT>>>(labels, task, N);

    dim3 sgrid(MAXSEG, RC);                        // (100, 8)
    segsum_kernel<<<sgrid, D4>>>((const float4*)z1, (const float4*)z2, task, out);

    gemm_loss_kernel<<<GLB, 256>>>(task, out);
}